// round 12
// baseline (speedup 1.0000x reference)
#include <cuda_runtime.h>
#include <cstdint>

#define NA  16
#define NR  32
#define TPB 128

// Rule-pair packed coefficient tables (built once by prep_kernel).
//   PQ[rp][k]  = (p[2rp,k],  p[2rp+1,k],  q[2rp,k],  q[2rp+1,k])
//   Cq[rp][kk] = (c[2rp,2kk],c[2rp+1,2kk],c[2rp,2kk+1],c[2rp+1,2kk+1])
//   RCC0[rp]   = (rc[2rp], rc[2rp+1], C0[2rp], C0[2rp+1])
struct CoefTab {
    float4 PQ[16][16];
    float4 Cq[16][8];
    float4 RCC0[16];
};
__device__ CoefTab gStage;

static __device__ __forceinline__ unsigned long long pack2(float lo, float hi) {
    unsigned long long r;
    asm("mov.b64 %0, {%1, %2};" : "=l"(r) : "f"(lo), "f"(hi));
    return r;
}
static __device__ __forceinline__ void unpack2(unsigned long long v, float& lo, float& hi) {
    asm("mov.b64 {%0, %1}, %2;" : "=f"(lo), "=f"(hi) : "l"(v));
}
static __device__ __forceinline__ unsigned long long fma2(
    unsigned long long a, unsigned long long b, unsigned long long c) {
    unsigned long long d;
    asm("fma.rn.f32x2 %0, %1, %2, %3;" : "=l"(d) : "l"(a), "l"(b), "l"(c));
    return d;
}
static __device__ __forceinline__ float ex2(float x) {
    float y;
    asm("ex2.approx.f32 %0, %1;" : "=f"(y) : "f"(x));
    return y;
}

// ---- prep kernel: 1 block, 256 threads ----
// Faithful to reference: idx = r*A + k; (sigma, center) = FRB_W[idx], FRB_W[idx+1]
__global__ void prep_kernel(const float* __restrict__ frbw,
                            const float* __restrict__ C)
{
    const float L2E = 1.4426950408889634f;
    int i = threadIdx.x;
    {   // 256 PQ entries
        int rp = i >> 4, k = i & 15;
        int r0 = 2 * rp, r1 = 2 * rp + 1;
        float sig0 = frbw[r0 * NA + k], cen0 = frbw[r0 * NA + k + 1];
        float sig1 = frbw[r1 * NA + k], cen1 = frbw[r1 * NA + k + 1];
        float is0 = 1.0f / (sig0 * sig0);
        float is1 = 1.0f / (sig1 * sig1);
        gStage.PQ[rp][k] = make_float4(-0.5f * is0 * L2E, -0.5f * is1 * L2E,
                                        is0 * cen0 * L2E,  is1 * cen1 * L2E);
    }
    if (i < 128) {   // 128 Cq entries
        int rp = i >> 3, kk = i & 7;
        gStage.Cq[rp][kk] = make_float4(C[(2 * rp)     * (NA + 1) + 2 * kk + 1],
                                        C[(2 * rp + 1) * (NA + 1) + 2 * kk + 1],
                                        C[(2 * rp)     * (NA + 1) + 2 * kk + 2],
                                        C[(2 * rp + 1) * (NA + 1) + 2 * kk + 2]);
    }
    if (i < 16) {    // per-rule-pair exponent constants and biases
        int r0 = 2 * i, r1 = 2 * i + 1;
        float a0 = 0.0f, a1 = 0.0f;
        for (int k = 0; k < NA; k++) {
            float s0 = frbw[r0 * NA + k], c0 = frbw[r0 * NA + k + 1];
            float s1 = frbw[r1 * NA + k], c1 = frbw[r1 * NA + k + 1];
            a0 += -0.5f / (s0 * s0) * L2E * c0 * c0;
            a1 += -0.5f / (s1 * s1) * L2E * c1 * c1;
        }
        gStage.RCC0[i] = make_float4(a0, a1,
                                     C[r0 * (NA + 1)], C[r1 * (NA + 1)]);
    }
}

// ---- main kernel: thread = 2 samples; table via __ldg (L1), rule-pair sweep ----
__global__ void __launch_bounds__(TPB)
tsk_kernel(const float* __restrict__ input,
           float* __restrict__ out, int B)
{
    const int t  = blockIdx.x * TPB + threadIdx.x;
    int sA = 2 * t, sB = 2 * t + 1;
    int rA = (sA < B) ? sA : (B - 1);
    int rB = (sB < B) ? sB : (B - 1);

    // two x rows as (x,x) dup pairs: 32 u64 = 64 regs
    const float4* xa = (const float4*)(input + (size_t)rA * NA);
    const float4* xb = (const float4*)(input + (size_t)rB * NA);
    unsigned long long XA[NA], XB[NA];
    #pragma unroll
    for (int j = 0; j < 4; j++) {
        float4 a = xa[j];
        float4 b = xb[j];
        XA[j * 4 + 0] = pack2(a.x, a.x);  XB[j * 4 + 0] = pack2(b.x, b.x);
        XA[j * 4 + 1] = pack2(a.y, a.y);  XB[j * 4 + 1] = pack2(b.y, b.y);
        XA[j * 4 + 2] = pack2(a.z, a.z);  XB[j * 4 + 2] = pack2(b.z, b.z);
        XA[j * 4 + 3] = pack2(a.w, a.w);  XB[j * 4 + 3] = pack2(b.w, b.w);
    }

    float numA = 0.0f, denA = 0.0f;
    float numB = 0.0f, denB = 0.0f;

    #pragma unroll 1     // body ~150 instrs: L0-resident, warp-uniform table addrs
    for (int rp = 0; rp < 16; rp++) {
        float4 rcc = __ldg(&gStage.RCC0[rp]);
        unsigned long long eA  = pack2(rcc.x, rcc.y);   // (rule 2rp | rule 2rp+1)
        unsigned long long eB  = eA;
        unsigned long long chA = pack2(rcc.z, rcc.w);
        unsigned long long chB = chA;
        const ulonglong2* pq = (const ulonglong2*)gStage.PQ[rp];
        const ulonglong2* cq = (const ulonglong2*)gStage.Cq[rp];
        #pragma unroll
        for (int kk = 0; kk < 8; kk++) {
            ulonglong2 w0 = __ldg(&pq[2 * kk]);       // (P k=2kk   | Q k=2kk)
            ulonglong2 w1 = __ldg(&pq[2 * kk + 1]);   // (P k=2kk+1 | Q k=2kk+1)
            ulonglong2 wc = __ldg(&cq[kk]);           // (C k=2kk   | C k=2kk+1)
            unsigned long long xae = XA[2 * kk], xao = XA[2 * kk + 1];
            unsigned long long xbe = XB[2 * kk], xbo = XB[2 * kk + 1];
            // k = 2kk
            unsigned long long tA0 = fma2(w0.x, xae, w0.y);
            unsigned long long tB0 = fma2(w0.x, xbe, w0.y);
            eA  = fma2(tA0, xae, eA);
            eB  = fma2(tB0, xbe, eB);
            chA = fma2(wc.x, xae, chA);
            chB = fma2(wc.x, xbe, chB);
            // k = 2kk+1
            unsigned long long tA1 = fma2(w1.x, xao, w1.y);
            unsigned long long tB1 = fma2(w1.x, xbo, w1.y);
            eA  = fma2(tA1, xao, eA);
            eB  = fma2(tB1, xbo, eB);
            chA = fma2(wc.y, xao, chA);
            chB = fma2(wc.y, xbo, chB);
        }
        float ea0, ea1, eb0, eb1, ca0, ca1, cb0, cb1;
        unpack2(eA, ea0, ea1);
        unpack2(eB, eb0, eb1);
        unpack2(chA, ca0, ca1);
        unpack2(chB, cb0, cb1);
        float ua0 = ex2(ea0), ua1 = ex2(ea1);
        float ub0 = ex2(eb0), ub1 = ex2(eb1);
        numA = fmaf(ua0, ca0, fmaf(ua1, ca1, numA));
        numB = fmaf(ub0, cb0, fmaf(ub1, cb1, numB));
        denA += ua0 + ua1;
        denB += ub0 + ub1;
    }

    if (sB < B) {
        *(float2*)(out + sA) = make_float2(__fdividef(numA, denA),
                                           __fdividef(numB, denB));
    } else if (sA < B) {
        out[sA] = __fdividef(numA, denA);
    }
}

extern "C" void kernel_launch(void* const* d_in, const int* in_sizes, int n_in,
                              void* d_out, int out_size)
{
    const float* input = (const float*)d_in[0];   // [B, 16] fp32
    const float* frbw  = (const float*)d_in[1];   // [1024]  fp32
    const float* Cm    = (const float*)d_in[2];   // [32,17] fp32
    float* out = (float*)d_out;                   // [B]     fp32

    int B = in_sizes[0] / NA;

    // 1) build packed rule-pair tables in device global (L1-resident, 13 KB)
    prep_kernel<<<1, 256>>>(frbw, Cm);
    // 2) main: 2 samples per thread
    int threads = (B + 1) / 2;
    int blocks = (threads + TPB - 1) / TPB;        // 256 for B=65536
    tsk_kernel<<<blocks, TPB>>>(input, out, B);
}

// round 13
// speedup vs baseline: 1.7633x; 1.7633x over previous
#include <cuda_runtime.h>
#include <cstdint>

#define NA   16
#define NR   32
#define TPB  128     // 4 warps; lane = rule, warp covers SPW samples
#define SPW  32      // samples per warp (512 blocks * 4 * 32 = 65536 exact)
#define XS   10      // u64 stride per staged sample row (80B, 16B-aligned)

static __device__ __forceinline__ unsigned long long pack2(float lo, float hi) {
    unsigned long long r;
    asm("mov.b64 %0, {%1, %2};" : "=l"(r) : "f"(lo), "f"(hi));
    return r;
}
static __device__ __forceinline__ void unpack2(unsigned long long v, float& lo, float& hi) {
    asm("mov.b64 {%0, %1}, %2;" : "=f"(lo), "=f"(hi) : "l"(v));
}
static __device__ __forceinline__ unsigned long long fma2(
    unsigned long long a, unsigned long long b, unsigned long long c) {
    unsigned long long d;
    asm("fma.rn.f32x2 %0, %1, %2, %3;" : "=l"(d) : "l"(a), "l"(b), "l"(c));
    return d;
}
static __device__ __forceinline__ float ex2(float x) {
    float y;
    asm("ex2.approx.f32 %0, %1;" : "=f"(y) : "f"(x));
    return y;
}

__global__ void __launch_bounds__(TPB, 4)
tsk_kernel(const float* __restrict__ input,
           const float* __restrict__ frbw,
           const float* __restrict__ C,
           float* __restrict__ out, int B)
{
    // Warp-private staging (+1 pad row so prefetch of s+1 never goes OOB).
    __shared__ unsigned long long sx[4][(SPW + 1) * XS];    // 10.6 KB
    __shared__ float rn[4][NR][33];                         // 16.9 KB
    __shared__ float rd[4][NR][33];                         // 16.9 KB

    const float L2E = 1.4426950408889634f;
    const int tid  = threadIdx.x;
    const int w    = tid >> 5;
    const int lane = tid & 31;
    const int ws0  = (blockIdx.x * 4 + w) * SPW;   // first sample of warp

    // ---- stage this warp's SPW rows (lane l -> row l) ----
    {
        int srow = ws0 + lane;
        if (srow >= B) srow = B - 1;               // clamp tail (exact for 65536)
        const float4* gsrc = (const float4*)(input + (size_t)srow * NA);
        float4* dst = (float4*)&sx[w][lane * XS];
        dst[0] = gsrc[0];
        dst[1] = gsrc[1];
        dst[2] = gsrc[2];
        dst[3] = gsrc[3];
    }

    // ---- per-lane rule coefficients (lane = rule), K-PACKED pairs: 24 u64 ----
    // Faithful to reference: idx = r*A + k; (sigma, center) = FRB_W[idx], FRB_W[idx+1]
    unsigned long long Pp[8], Qp[8], Cp[8];
    float rce = 0.0f, rco = 0.0f;
    const float* wr = frbw + lane * NA;
    const float* cr = C + lane * (NA + 1);
    #pragma unroll
    for (int j = 0; j < 8; j++) {
        float sig0 = __ldg(wr + 2 * j);
        float cen0 = __ldg(wr + 2 * j + 1);
        float is20 = 1.0f / (sig0 * sig0);
        float p0 = -0.5f * is20 * L2E;
        float q0 = is20 * cen0 * L2E;
        float sig1 = __ldg(wr + 2 * j + 1);
        float cen1 = __ldg(wr + 2 * j + 2);
        float is21 = 1.0f / (sig1 * sig1);
        float p1 = -0.5f * is21 * L2E;
        float q1 = is21 * cen1 * L2E;
        Pp[j] = pack2(p0, p1);
        Qp[j] = pack2(q0, q1);
        Cp[j] = pack2(__ldg(cr + 2 * j + 1), __ldg(cr + 2 * j + 2));
        rce += p0 * cen0 * cen0;
        rco += p1 * cen1 * cen1;
    }
    const unsigned long long RC = pack2(rce, rco);          // exponent const (even,odd)
    const unsigned long long C0 = pack2(__ldg(cr), 0.0f);   // bias in even slot

    __syncwarp();   // staging visible warp-wide

    const unsigned long long* xw = sx[w];

    // ---- main loop: double-buffered X (prefetch s+1 while computing s) ----
    ulonglong2 x0, x1, x2, x3;
    {
        const ulonglong2* xp = (const ulonglong2*)xw;
        x0 = xp[0]; x1 = xp[1]; x2 = xp[2]; x3 = xp[3];
    }

    #pragma unroll 2
    for (int s = 0; s < SPW; s++) {
        // rotate current, issue prefetch of s+1 (pad row makes s=31 safe)
        ulonglong2 c0 = x0, c1 = x1, c2 = x2, c3 = x3;
        {
            const ulonglong2* xn = (const ulonglong2*)(xw + (s + 1) * XS);
            x0 = xn[0]; x1 = xn[1]; x2 = xn[2]; x3 = xn[3];
        }

        unsigned long long e  = RC;
        unsigned long long ch = C0;
        // c0 covers k=0..3, c1 k=4..7, c2 k=8..11, c3 k=12..15 (k-packed pairs)
        {
            unsigned long long t;
            t = fma2(Pp[0], c0.x, Qp[0]);  e = fma2(t, c0.x, e);  ch = fma2(Cp[0], c0.x, ch);
            t = fma2(Pp[1], c0.y, Qp[1]);  e = fma2(t, c0.y, e);  ch = fma2(Cp[1], c0.y, ch);
            t = fma2(Pp[2], c1.x, Qp[2]);  e = fma2(t, c1.x, e);  ch = fma2(Cp[2], c1.x, ch);
            t = fma2(Pp[3], c1.y, Qp[3]);  e = fma2(t, c1.y, e);  ch = fma2(Cp[3], c1.y, ch);
            t = fma2(Pp[4], c2.x, Qp[4]);  e = fma2(t, c2.x, e);  ch = fma2(Cp[4], c2.x, ch);
            t = fma2(Pp[5], c2.y, Qp[5]);  e = fma2(t, c2.y, e);  ch = fma2(Cp[5], c2.y, ch);
            t = fma2(Pp[6], c3.x, Qp[6]);  e = fma2(t, c3.x, e);  ch = fma2(Cp[6], c3.x, ch);
            t = fma2(Pp[7], c3.y, Qp[7]);  e = fma2(t, c3.y, e);  ch = fma2(Cp[7], c3.y, ch);
        }

        float ee, eo, che, cho;
        unpack2(e, ee, eo);
        unpack2(ch, che, cho);
        float u = ex2(ee + eo);            // rule firing strength (this lane's rule)
        float chs = che + cho;
        // fire-and-forget partials (conflict-free: bank = (lane*33+s) % 32 = lane+s)
        rn[w][lane][s] = u * chs;
        rd[w][lane][s] = u;
    }

    __syncwarp();

    // ---- reduction: lane = sample, sum over 32 rules (conflict-free columns) ----
    {
        float n0 = 0.f, n1 = 0.f, n2 = 0.f, n3 = 0.f;
        float d0 = 0.f, d1 = 0.f, d2 = 0.f, d3 = 0.f;
        #pragma unroll
        for (int r = 0; r < NR; r += 4) {
            n0 += rn[w][r + 0][lane];
            n1 += rn[w][r + 1][lane];
            n2 += rn[w][r + 2][lane];
            n3 += rn[w][r + 3][lane];
            d0 += rd[w][r + 0][lane];
            d1 += rd[w][r + 1][lane];
            d2 += rd[w][r + 2][lane];
            d3 += rd[w][r + 3][lane];
        }
        float num = (n0 + n1) + (n2 + n3);
        float den = (d0 + d1) + (d2 + d3);
        int s = ws0 + lane;
        if (s < B) out[s] = __fdividef(num, den);
    }
}

extern "C" void kernel_launch(void* const* d_in, const int* in_sizes, int n_in,
                              void* d_out, int out_size)
{
    const float* input = (const float*)d_in[0];   // [B, 16] fp32
    const float* frbw  = (const float*)d_in[1];   // [1024]  fp32
    const float* Cm    = (const float*)d_in[2];   // [32,17] fp32
    float* out = (float*)d_out;                   // [B]     fp32

    int B = in_sizes[0] / NA;
    int spb = 4 * SPW;                             // 128 samples per block
    int blocks = (B + spb - 1) / spb;              // 512 for B=65536 (exact)
    tsk_kernel<<<blocks, TPB>>>(input, frbw, Cm, out, B);
}

// round 14
// speedup vs baseline: 1.9766x; 1.1210x over previous
#include <cuda_runtime.h>
#include <cstdint>

#define NA   16
#define NR   32
#define TPB  64      // 2 warps/block
#define SPT  4       // samples per thread (thread-private, register-resident)
#define SPB  (TPB * SPT)   // 256 samples per block

static __device__ __forceinline__ unsigned long long pack2(float lo, float hi) {
    unsigned long long r;
    asm("mov.b64 %0, {%1, %2};" : "=l"(r) : "f"(lo), "f"(hi));
    return r;
}
static __device__ __forceinline__ void unpack2(unsigned long long v, float& lo, float& hi) {
    asm("mov.b64 {%0, %1}, %2;" : "=f"(lo), "=f"(hi) : "l"(v));
}
static __device__ __forceinline__ unsigned long long fma2(
    unsigned long long a, unsigned long long b, unsigned long long c) {
    unsigned long long d;
    asm("fma.rn.f32x2 %0, %1, %2, %3;" : "=l"(d) : "l"(a), "l"(b), "l"(c));
    return d;
}
static __device__ __forceinline__ float ex2(float x) {
    float y;
    asm("ex2.approx.f32 %0, %1;" : "=f"(y) : "f"(x));
    return y;
}

__global__ void __launch_bounds__(TPB)
tsk_kernel(const float* __restrict__ input,
           const float* __restrict__ frbw,
           const float* __restrict__ C,
           float* __restrict__ out, int B)
{
    // Coefficient table, k-packed u64 pairs, built once per block (~6.9 KB).
    // Per rule r: [0..7]=P pairs, [8..15]=Q pairs, [16..23]=C pairs,
    //             [24]=(rc_even, rc_odd), [25]=(C0, 0).
    __shared__ unsigned long long sco[NR][27];

    const float L2E = 1.4426950408889634f;
    const int tid = threadIdx.x;

    // ---- build coefficient table (once per block; 4 kpair slots/thread) ----
    // Faithful to reference: idx = r*A + k; (sigma, center) = FRB_W[idx], FRB_W[idx+1]
    for (int i = tid; i < NR * 8; i += TPB) {
        int r = i >> 3, j = i & 7;
        int k0 = 2 * j;
        float sig0 = frbw[r * NA + k0];
        float cen0 = frbw[r * NA + k0 + 1];
        float is0 = 1.0f / (sig0 * sig0);
        float p0 = -0.5f * is0 * L2E;
        float q0 = is0 * cen0 * L2E;
        float sig1 = frbw[r * NA + k0 + 1];
        float cen1 = frbw[r * NA + k0 + 2];
        float is1 = 1.0f / (sig1 * sig1);
        float p1 = -0.5f * is1 * L2E;
        float q1 = is1 * cen1 * L2E;
        sco[r][j]      = pack2(p0, p1);
        sco[r][8 + j]  = pack2(q0, q1);
        sco[r][16 + j] = pack2(C[r * (NA + 1) + k0 + 1], C[r * (NA + 1) + k0 + 2]);
    }
    if (tid < NR) {
        int r = tid;
        float rce = 0.0f, rco = 0.0f;
        #pragma unroll
        for (int j = 0; j < 8; j++) {
            float sig0 = frbw[r * NA + 2 * j];
            float cen0 = frbw[r * NA + 2 * j + 1];
            rce += -0.5f / (sig0 * sig0) * L2E * cen0 * cen0;
            float sig1 = frbw[r * NA + 2 * j + 1];
            float cen1 = frbw[r * NA + 2 * j + 2];
            rco += -0.5f / (sig1 * sig1) * L2E * cen1 * cen1;
        }
        sco[r][24] = pack2(rce, rco);
        sco[r][25] = pack2(C[r * (NA + 1)], 0.0f);
    }
    __syncthreads();

    // ---- thread-private X: 4 interleaved rows, k-packed pairs (32 u64) ----
    const int base = blockIdx.x * SPB;
    int row[SPT];
    unsigned long long X[SPT][8];
    #pragma unroll
    for (int i = 0; i < SPT; i++) {
        int rr = base + tid + TPB * i;
        row[i] = rr;
        int cl = (rr < B) ? rr : (B - 1);
        const float4* g = (const float4*)(input + (size_t)cl * NA);
        float4 v0 = g[0], v1 = g[1], v2 = g[2], v3 = g[3];
        X[i][0] = pack2(v0.x, v0.y);  X[i][1] = pack2(v0.z, v0.w);
        X[i][2] = pack2(v1.x, v1.y);  X[i][3] = pack2(v1.z, v1.w);
        X[i][4] = pack2(v2.x, v2.y);  X[i][5] = pack2(v2.z, v2.w);
        X[i][6] = pack2(v3.x, v3.y);  X[i][7] = pack2(v3.z, v3.w);
    }

    float num[SPT] = {0.f, 0.f, 0.f, 0.f};
    float den[SPT] = {0.f, 0.f, 0.f, 0.f};

    // ---- sweep 32 rules; coefficients amortized over 128 samples/warp ----
    #pragma unroll 1      // body ~170 instrs: L0-resident
    for (int r = 0; r < NR; r++) {
        const unsigned long long* cw = sco[r];   // broadcast LDS (warp-uniform)
        unsigned long long RC = cw[24];
        unsigned long long C0 = cw[25];
        unsigned long long e0 = RC, e1 = RC, e2 = RC, e3 = RC;
        unsigned long long h0 = C0, h1 = C0, h2 = C0, h3 = C0;
        #pragma unroll
        for (int k = 0; k < 8; k++) {
            unsigned long long Pk = cw[k];
            unsigned long long Qk = cw[8 + k];
            unsigned long long Ck = cw[16 + k];
            unsigned long long t0 = fma2(Pk, X[0][k], Qk);
            unsigned long long t1 = fma2(Pk, X[1][k], Qk);
            unsigned long long t2 = fma2(Pk, X[2][k], Qk);
            unsigned long long t3 = fma2(Pk, X[3][k], Qk);
            e0 = fma2(t0, X[0][k], e0);
            e1 = fma2(t1, X[1][k], e1);
            e2 = fma2(t2, X[2][k], e2);
            e3 = fma2(t3, X[3][k], e3);
            h0 = fma2(Ck, X[0][k], h0);
            h1 = fma2(Ck, X[1][k], h1);
            h2 = fma2(Ck, X[2][k], h2);
            h3 = fma2(Ck, X[3][k], h3);
        }
        float ae, ao, be, bo, ce, co, de, dofs;
        float he0, ho0, he1, ho1, he2, ho2, he3, ho3;
        unpack2(e0, ae, ao);  unpack2(e1, be, bo);
        unpack2(e2, ce, co);  unpack2(e3, de, dofs);
        unpack2(h0, he0, ho0);  unpack2(h1, he1, ho1);
        unpack2(h2, he2, ho2);  unpack2(h3, he3, ho3);
        float u0 = ex2(ae + ao);
        float u1 = ex2(be + bo);
        float u2 = ex2(ce + co);
        float u3 = ex2(de + dofs);
        num[0] = fmaf(u0, he0 + ho0, num[0]);  den[0] += u0;
        num[1] = fmaf(u1, he1 + ho1, num[1]);  den[1] += u1;
        num[2] = fmaf(u2, he2 + ho2, num[2]);  den[2] += u2;
        num[3] = fmaf(u3, he3 + ho3, num[3]);  den[3] += u3;
    }

    #pragma unroll
    for (int i = 0; i < SPT; i++) {
        if (row[i] < B) out[row[i]] = __fdividef(num[i], den[i]);  // coalesced
    }
}

extern "C" void kernel_launch(void* const* d_in, const int* in_sizes, int n_in,
                              void* d_out, int out_size)
{
    const float* input = (const float*)d_in[0];   // [B, 16] fp32
    const float* frbw  = (const float*)d_in[1];   // [1024]  fp32
    const float* Cm    = (const float*)d_in[2];   // [32,17] fp32
    float* out = (float*)d_out;                   // [B]     fp32

    int B = in_sizes[0] / NA;
    int blocks = (B + SPB - 1) / SPB;             // 256 for B=65536
    tsk_kernel<<<blocks, TPB>>>(input, frbw, Cm, out, B);
}

// round 15
// speedup vs baseline: 2.0065x; 1.0151x over previous
#include <cuda_runtime.h>
#include <cstdint>

#define NA   16
#define NR   32
#define TPB  128     // 4 warps; warp w handles rules 8w..8w+7
#define RPW  8       // rules per warp
#define SPT  4       // samples per thread
#define SPB  128     // samples per block (32 lanes * SPT, shared by all 4 warps)

static __device__ __forceinline__ unsigned long long pack2(float lo, float hi) {
    unsigned long long r;
    asm("mov.b64 %0, {%1, %2};" : "=l"(r) : "f"(lo), "f"(hi));
    return r;
}
static __device__ __forceinline__ void unpack2(unsigned long long v, float& lo, float& hi) {
    asm("mov.b64 {%0, %1}, %2;" : "=f"(lo), "=f"(hi) : "l"(v));
}
static __device__ __forceinline__ unsigned long long fma2(
    unsigned long long a, unsigned long long b, unsigned long long c) {
    unsigned long long d;
    asm("fma.rn.f32x2 %0, %1, %2, %3;" : "=l"(d) : "l"(a), "l"(b), "l"(c));
    return d;
}
static __device__ __forceinline__ float ex2(float x) {
    float y;
    asm("ex2.approx.f32 %0, %1;" : "=f"(y) : "f"(x));
    return y;
}

__global__ void __launch_bounds__(TPB, 4)
tsk_kernel(const float* __restrict__ input,
           const float* __restrict__ frbw,
           const float* __restrict__ C,
           float* __restrict__ out, int B)
{
    // Coefficient table, k-packed u64 pairs (~6.9 KB), built once per block.
    // Per rule r: [0..7]=P pairs, [8..15]=Q pairs, [16..23]=C pairs,
    //             [24]=(rc_even, rc_odd), [25]=(C0, 0).
    __shared__ unsigned long long sco[NR][26];
    // Rule-group partials: red[group][spt][lane] = (num, den)
    __shared__ float2 red[4][SPT][32];

    const float L2E = 1.4426950408889634f;
    const int tid  = threadIdx.x;
    const int w    = tid >> 5;
    const int lane = tid & 31;

    // ---- build coefficient table (2 kpair slots/thread) ----
    // Faithful to reference: idx = r*A + k; (sigma, center) = FRB_W[idx], FRB_W[idx+1]
    for (int i = tid; i < NR * 8; i += TPB) {
        int r = i >> 3, j = i & 7;
        int k0 = 2 * j;
        float sig0 = frbw[r * NA + k0];
        float cen0 = frbw[r * NA + k0 + 1];
        float is0 = 1.0f / (sig0 * sig0);
        float p0 = -0.5f * is0 * L2E;
        float q0 = is0 * cen0 * L2E;
        float sig1 = frbw[r * NA + k0 + 1];
        float cen1 = frbw[r * NA + k0 + 2];
        float is1 = 1.0f / (sig1 * sig1);
        float p1 = -0.5f * is1 * L2E;
        float q1 = is1 * cen1 * L2E;
        sco[r][j]      = pack2(p0, p1);
        sco[r][8 + j]  = pack2(q0, q1);
        sco[r][16 + j] = pack2(C[r * (NA + 1) + k0 + 1], C[r * (NA + 1) + k0 + 2]);
    }
    if (tid < NR) {
        int r = tid;
        float rce = 0.0f, rco = 0.0f;
        #pragma unroll
        for (int j = 0; j < 8; j++) {
            float sig0 = frbw[r * NA + 2 * j];
            float cen0 = frbw[r * NA + 2 * j + 1];
            rce += -0.5f / (sig0 * sig0) * L2E * cen0 * cen0;
            float sig1 = frbw[r * NA + 2 * j + 1];
            float cen1 = frbw[r * NA + 2 * j + 2];
            rco += -0.5f / (sig1 * sig1) * L2E * cen1 * cen1;
        }
        sco[r][24] = pack2(rce, rco);
        sco[r][25] = pack2(C[r * (NA + 1)], 0.0f);
    }
    __syncthreads();

    // ---- thread-private X: SPT rows (same 128 samples in all 4 warps) ----
    const int base = blockIdx.x * SPB;
    unsigned long long X[SPT][8];
    #pragma unroll
    for (int i = 0; i < SPT; i++) {
        int rr = base + lane + 32 * i;
        int cl = (rr < B) ? rr : (B - 1);
        const float4* g = (const float4*)(input + (size_t)cl * NA);
        float4 v0 = g[0], v1 = g[1], v2 = g[2], v3 = g[3];
        X[i][0] = pack2(v0.x, v0.y);  X[i][1] = pack2(v0.z, v0.w);
        X[i][2] = pack2(v1.x, v1.y);  X[i][3] = pack2(v1.z, v1.w);
        X[i][4] = pack2(v2.x, v2.y);  X[i][5] = pack2(v2.z, v2.w);
        X[i][6] = pack2(v3.x, v3.y);  X[i][7] = pack2(v3.z, v3.w);
    }

    float num[SPT] = {0.f, 0.f, 0.f, 0.f};
    float den[SPT] = {0.f, 0.f, 0.f, 0.f};

    // ---- sweep this warp's 8 rules; coeffs amortized over 128 samples ----
    const int r0 = w * RPW;
    #pragma unroll 1      // body ~170 instrs: L0-resident
    for (int r = r0; r < r0 + RPW; r++) {
        const unsigned long long* cw = sco[r];   // warp-uniform broadcast LDS
        unsigned long long RC = cw[24];
        unsigned long long C0 = cw[25];
        unsigned long long e0 = RC, e1 = RC, e2 = RC, e3 = RC;
        unsigned long long h0 = C0, h1 = C0, h2 = C0, h3 = C0;
        #pragma unroll
        for (int k = 0; k < 8; k++) {
            unsigned long long Pk = cw[k];
            unsigned long long Qk = cw[8 + k];
            unsigned long long Ck = cw[16 + k];
            unsigned long long t0 = fma2(Pk, X[0][k], Qk);
            unsigned long long t1 = fma2(Pk, X[1][k], Qk);
            unsigned long long t2 = fma2(Pk, X[2][k], Qk);
            unsigned long long t3 = fma2(Pk, X[3][k], Qk);
            e0 = fma2(t0, X[0][k], e0);
            e1 = fma2(t1, X[1][k], e1);
            e2 = fma2(t2, X[2][k], e2);
            e3 = fma2(t3, X[3][k], e3);
            h0 = fma2(Ck, X[0][k], h0);
            h1 = fma2(Ck, X[1][k], h1);
            h2 = fma2(Ck, X[2][k], h2);
            h3 = fma2(Ck, X[3][k], h3);
        }
        float ae, ao, be, bo, ce, co, de, df;
        float he0, ho0, he1, ho1, he2, ho2, he3, ho3;
        unpack2(e0, ae, ao);  unpack2(e1, be, bo);
        unpack2(e2, ce, co);  unpack2(e3, de, df);
        unpack2(h0, he0, ho0);  unpack2(h1, he1, ho1);
        unpack2(h2, he2, ho2);  unpack2(h3, he3, ho3);
        float u0 = ex2(ae + ao);
        float u1 = ex2(be + bo);
        float u2 = ex2(ce + co);
        float u3 = ex2(de + df);
        num[0] = fmaf(u0, he0 + ho0, num[0]);  den[0] += u0;
        num[1] = fmaf(u1, he1 + ho1, num[1]);  den[1] += u1;
        num[2] = fmaf(u2, he2 + ho2, num[2]);  den[2] += u2;
        num[3] = fmaf(u3, he3 + ho3, num[3]);  den[3] += u3;
    }

    // ---- combine rule-group partials across the 4 warps ----
    #pragma unroll
    for (int i = 0; i < SPT; i++) red[w][i][lane] = make_float2(num[i], den[i]);
    __syncthreads();

    // thread (w, lane) outputs sample slot i = w for lane `lane`
    {
        float2 p0 = red[0][w][lane];
        float2 p1 = red[1][w][lane];
        float2 p2 = red[2][w][lane];
        float2 p3 = red[3][w][lane];
        float n = (p0.x + p1.x) + (p2.x + p3.x);
        float d = (p0.y + p1.y) + (p2.y + p3.y);
        int s = base + lane + 32 * w;   // coalesced per warp
        if (s < B) out[s] = __fdividef(n, d);
    }
}

extern "C" void kernel_launch(void* const* d_in, const int* in_sizes, int n_in,
                              void* d_out, int out_size)
{
    const float* input = (const float*)d_in[0];   // [B, 16] fp32
    const float* frbw  = (const float*)d_in[1];   // [1024]  fp32
    const float* Cm    = (const float*)d_in[2];   // [32,17] fp32
    float* out = (float*)d_out;                   // [B]     fp32

    int B = in_sizes[0] / NA;
    int blocks = (B + SPB - 1) / SPB;             // 512 for B=65536 (exact)
    tsk_kernel<<<blocks, TPB>>>(input, frbw, Cm, out, B);
}